// round 5
// baseline (speedup 1.0000x reference)
#include <cuda_runtime.h>
#include <cstdint>

#define Hh 128
#define Ww 128
#define LL 16384          // H*W
#define NB 2
#define NC1 64
#define NC2 128
#define OUT_LV2_ELEMS 4194304
#define SENT 16384        // sentinel tap offset -> zero slot

// Scratch
__device__ int            g_idx[NB * LL];                      // 128 KB
__device__ unsigned short g_tab[NB * 9 * LL];                  // 576 KB tap offsets
__device__ float4         g_blk2[(size_t)NB * (LL + 1) * 64];  // +1 zero cell per b

// ---------------------------------------------------------------------------
// k_idx: detect index dtype (jax may canonicalize int64->int32), extract low
// words, and zero the sentinel cells of g_blk2.
// ---------------------------------------------------------------------------
__global__ void k_idx(const int* __restrict__ hw) {
    __shared__ int s_or;
    if (threadIdx.x == 0) s_or = 0;
    __syncthreads();
    int acc = 0;
#pragma unroll
    for (int k = 0; k < 8; k++) acc |= hw[2 * (threadIdx.x + (k << 8)) + 1];
    if (acc) atomicOr(&s_or, 1);
    __syncthreads();
    int stride = s_or ? 1 : 2;
    int i = blockIdx.x * blockDim.x + threadIdx.x;
    g_idx[i] = hw[i * stride];
    if (blockIdx.x == 0 && threadIdx.x < 128) {
        int b = threadIdx.x >> 6, c = threadIdx.x & 63;
        g_blk2[((size_t)b * (LL + 1) + LL) * 64 + c] = make_float4(0.f, 0.f, 0.f, 0.f);
    }
}

// ---------------------------------------------------------------------------
// k_tab: shared tap-offset table for BOTH gather kernels.
// tab[(b*9+tap)*LL + p] = source plane offset (or SENT if either bound fails).
// ---------------------------------------------------------------------------
__global__ void k_tab() {
    int gp = blockIdx.x * blockDim.x + threadIdx.x;   // 0..32767
    int b  = gp >> 14;
    int p  = gp & (LL - 1);
    int y = p >> 7, x = p & 127;
    const int* idxb = g_idx + (b << 14);
    unsigned short* tb = g_tab + (size_t)b * 9 * LL;
#pragma unroll
    for (int dy = -1; dy <= 1; dy++) {
#pragma unroll
        for (int dx = -1; dx <= 1; dx++) {
            int tap = (dy + 1) * 3 + (dx + 1);
            int oy = y - dy, ox = x - dx;
            unsigned short off = SENT;
            if ((unsigned)oy < Hh && (unsigned)ox < Ww) {
                int m  = idxb[(oy << 7) + ox];
                int sr = (m >> 7)  + dy;
                int sc = (m & 127) + dx;
                if ((unsigned)sr < Hh && (unsigned)sc < Ww)
                    off = (unsigned short)((sr << 7) + sc);
            }
            tb[tap * LL + p] = off;
        }
    }
}

// ---------------------------------------------------------------------------
// k_blk: space-to-depth transpose of lv1 into channel-innermost blocked layout.
// g_blk2[(b*(LL+1) + cell)*64 + c] = float4{p00,p01,p10,p11} of channel c.
// ---------------------------------------------------------------------------
__global__ void k_blk(const float* __restrict__ lv1) {
    __shared__ float4 s4[64 * 33];
    float2* s2 = (float2*)s4;                 // row stride 66 float2 per c
    int bid = blockIdx.x;                     // 2*128*4 = 1024
    int vt = bid & 3;
    int mh = (bid >> 2) & 127;
    int b  = bid >> 9;
    int v0 = vt << 5;

#pragma unroll
    for (int k = 0; k < 8; k++) {
        int j  = threadIdx.x + (k << 8);
        int c  = j >> 5;
        int dy = (j >> 4) & 1;
        int x4 = j & 15;
        const float4 val = *(const float4*)(lv1 + (((size_t)(b * NC1 + c)) << 16)
                                            + ((2 * mh + dy) << 8) + (v0 << 1) + (x4 << 2));
        int vl0 = x4 << 1;
        s2[c * 66 + (vl0 << 1) + dy]     = make_float2(val.x, val.y);
        s2[c * 66 + (vl0 << 1) + 2 + dy] = make_float2(val.z, val.w);
    }
    __syncthreads();

    float4* dst = g_blk2 + ((size_t)b * (LL + 1) + (mh << 7) + v0) * 64;
#pragma unroll
    for (int k = 0; k < 8; k++) {
        int j  = threadIdx.x + (k << 8);
        int vl = j >> 6;
        int c  = j & 63;
        dst[(size_t)vl * 64 + c] = s4[c * 33 + vl];
    }
}

// ---------------------------------------------------------------------------
// k_lv2: plane-resident SMEM gather driven by the tap table. No bounds math,
// no idx loads: 9 LDG.U16 + 9 LDS.64 + FADDs per pixel. Slot SENT is zero.
// ---------------------------------------------------------------------------
__global__ void k_lv2(const float* __restrict__ lv2, float* __restrict__ out) {
    extern __shared__ float2 s_plane[];              // (16384+1) float2
    int bcp = blockIdx.x;
    int cp  = bcp & 63;
    int b   = bcp >> 6;
    const float* base0 = lv2 + ((size_t)(b * NC2 + cp * 2) << 14);
    for (int i = threadIdx.x; i < LL; i += blockDim.x)
        s_plane[i] = make_float2(base0[i], base0[i + LL]);
    if (threadIdx.x == 0) s_plane[SENT] = make_float2(0.f, 0.f);
    __syncthreads();

    const unsigned short* tb = g_tab + (size_t)b * 9 * LL;
    float* out0 = out + ((size_t)(b * NC2 + cp * 2) << 14);
    const float inv9 = 1.0f / 9.0f;

#pragma unroll
    for (int it = 0; it < 8; it++) {
        int p1 = threadIdx.x + (it << 11);
        int p2 = p1 + 1024;
        float a0 = 0.f, a1 = 0.f, b0 = 0.f, b1 = 0.f;
#pragma unroll
        for (int tap = 0; tap < 9; tap++) {
            float2 v = s_plane[tb[tap * LL + p1]];
            float2 w = s_plane[tb[tap * LL + p2]];
            a0 += v.x; a1 += v.y;
            b0 += w.x; b1 += w.y;
        }
        out0[p1]      = a0 * inv9;
        out0[p1 + LL] = a1 * inv9;
        out0[p2]      = b0 * inv9;
        out0[p2 + LL] = b1 * inv9;
    }
}

// ---------------------------------------------------------------------------
// k_lv1: warp-per-cell gather, lanes = 32 channels. Per cell: 9 warp-uniform
// table loads + 9 unconditional coalesced 512B LDG.128 + sum tree. Sentinel
// offset hits the zeroed extra cell, so no predication at all.
// ---------------------------------------------------------------------------
__global__ void __launch_bounds__(256, 3) k_lv1(float* __restrict__ out) {
    extern __shared__ float2 sh2[];           // 64 rows x 65 float2 = 33280 B
    int bid  = blockIdx.x;                    // 2*128*2*2 = 1024
    int half = bid & 1;
    int vt   = (bid >> 1) & 1;
    int u    = (bid >> 2) & 127;
    int b    = bid >> 9;
    int v0   = vt << 6;
    int w    = threadIdx.x >> 5;
    int lane = threadIdx.x & 31;
    const unsigned short* tb = g_tab + (size_t)b * 9 * LL;
    const float4* blkb = g_blk2 + ((size_t)b * (LL + 1)) * 64 + (half << 5) + lane;
    const float inv9 = 1.0f / 9.0f;

#pragma unroll
    for (int jj = 0; jj < 8; jj++) {
        int j = (w << 3) + jj;                // local cell 0..63
        int cell = (u << 7) + v0 + j;
        float4 t[9];
#pragma unroll
        for (int tap = 0; tap < 9; tap++) {
            unsigned off = tb[tap * LL + cell];          // warp-uniform
            t[tap] = blkb[((size_t)off) << 6];
        }
        float4 A;
        A.x = ((t[0].x + t[1].x) + (t[2].x + t[3].x)) + ((t[4].x + t[5].x) + (t[6].x + t[7].x)) + t[8].x;
        A.y = ((t[0].y + t[1].y) + (t[2].y + t[3].y)) + ((t[4].y + t[5].y) + (t[6].y + t[7].y)) + t[8].y;
        A.z = ((t[0].z + t[1].z) + (t[2].z + t[3].z)) + ((t[4].z + t[5].z) + (t[6].z + t[7].z)) + t[8].z;
        A.w = ((t[0].w + t[1].w) + (t[2].w + t[3].w)) + ((t[4].w + t[5].w) + (t[6].w + t[7].w)) + t[8].w;
        sh2[lane * 65 + j]        = make_float2(A.x * inv9, A.y * inv9);
        sh2[(32 + lane) * 65 + j] = make_float2(A.z * inv9, A.w * inv9);
    }
    __syncthreads();

    // Copy-out: warp per row (64 rows), coalesced 256B float2 stores.
    for (int r = w; r < 64; r += 8) {
        int py = r >> 5;
        int c  = r & 31;
        float2* orow = (float2*)(out + (((size_t)(b * NC1 + (half << 5) + c)) << 16)
                                 + ((2 * u + py) << 8) + (v0 << 1));
        const float2* srow = sh2 + r * 65;
        orow[lane]      = srow[lane];
        orow[lane + 32] = srow[lane + 32];
    }
}

// ---------------------------------------------------------------------------
extern "C" void kernel_launch(void* const* d_in, const int* in_sizes, int n_in,
                              void* d_out, int out_size) {
    const float* lv1 = nullptr;   // 8388608
    const float* lv2 = nullptr;   // 4194304
    const int*   hix = nullptr;   // 32768
    for (int i = 0; i < n_in; i++) {
        if (in_sizes[i] == 8388608)      lv1 = (const float*)d_in[i];
        else if (in_sizes[i] == 4194304) lv2 = (const float*)d_in[i];
        else if (in_sizes[i] == 32768)   hix = (const int*)d_in[i];
    }
    float* out = (float*)d_out;

    cudaFuncSetAttribute(k_lv2, cudaFuncAttributeMaxDynamicSharedMemorySize, 131080);
    cudaFuncSetAttribute(k_lv1, cudaFuncAttributeMaxDynamicSharedMemorySize, 33280);

    k_idx<<<128, 256>>>(hix);
    k_blk<<<1024, 256>>>(lv1);
    k_tab<<<128, 256>>>();
    k_lv2<<<128, 1024, 131080>>>(lv2, out);
    k_lv1<<<1024, 256, 33280>>>(out + OUT_LV2_ELEMS);
}

// round 6
// speedup vs baseline: 1.2863x; 1.2863x over previous
#include <cuda_runtime.h>
#include <cuda_fp16.h>
#include <cstdint>

#define Hh 128
#define Ww 128
#define LL 16384          // H*W
#define NB 2
#define NC1 64
#define NC2 128
#define OUT_LV2_ELEMS 4194304
#define SENT 16384        // sentinel tap offset -> zero slot

// Scratch
__device__ int            g_idx[NB * LL];                      // 128 KB
__device__ unsigned short g_tab[NB * 9 * LL];                  // 576 KB tap offsets
__device__ uint2          g_blkh[(size_t)NB * (LL + 1) * 64];  // 16.8 MB half4 blocks

// ---------------------------------------------------------------------------
// k_idx: detect index dtype (jax may canonicalize int64->int32), extract low
// words, and zero the sentinel cells of g_blkh.
// ---------------------------------------------------------------------------
__global__ void k_idx(const int* __restrict__ hw) {
    __shared__ int s_or;
    if (threadIdx.x == 0) s_or = 0;
    __syncthreads();
    int acc = 0;
#pragma unroll
    for (int k = 0; k < 8; k++) acc |= hw[2 * (threadIdx.x + (k << 8)) + 1];
    if (acc) atomicOr(&s_or, 1);
    __syncthreads();
    int stride = s_or ? 1 : 2;
    int i = blockIdx.x * blockDim.x + threadIdx.x;
    g_idx[i] = hw[i * stride];
    if (blockIdx.x == 0 && threadIdx.x < 128) {
        int b = threadIdx.x >> 6, c = threadIdx.x & 63;
        g_blkh[((size_t)b * (LL + 1) + LL) * 64 + c] = make_uint2(0u, 0u);
    }
}

// ---------------------------------------------------------------------------
// k_tab: shared tap-offset table for BOTH gather kernels.
// tab[(b*9+tap)*LL + p] = source plane offset (or SENT if either bound fails).
// ---------------------------------------------------------------------------
__global__ void k_tab() {
    int gp = blockIdx.x * blockDim.x + threadIdx.x;   // 0..32767
    int b  = gp >> 14;
    int p  = gp & (LL - 1);
    int y = p >> 7, x = p & 127;
    const int* idxb = g_idx + (b << 14);
    unsigned short* tb = g_tab + (size_t)b * 9 * LL;
#pragma unroll
    for (int dy = -1; dy <= 1; dy++) {
#pragma unroll
        for (int dx = -1; dx <= 1; dx++) {
            int tap = (dy + 1) * 3 + (dx + 1);
            int oy = y - dy, ox = x - dx;
            unsigned short off = SENT;
            if ((unsigned)oy < Hh && (unsigned)ox < Ww) {
                int m  = idxb[(oy << 7) + ox];
                int sr = (m >> 7)  + dy;
                int sc = (m & 127) + dx;
                if ((unsigned)sr < Hh && (unsigned)sc < Ww)
                    off = (unsigned short)((sr << 7) + sc);
            }
            tb[tap * LL + p] = off;
        }
    }
}

// ---------------------------------------------------------------------------
// k_blk: space-to-depth transpose of lv1 -> fp16 channel-innermost blocks.
// g_blkh[(b*(LL+1)+cell)*64 + c] = uint2{h2(p00,p01), h2(p10,p11)} of channel c.
// Staged in SMEM as uint2 rows stride 33 (<=2-way banks both phases).
// ---------------------------------------------------------------------------
__global__ void k_blk(const float* __restrict__ lv1) {
    __shared__ uint2 s2h[64 * 33];
    unsigned* sw = (unsigned*)s2h;
    int bid = blockIdx.x;                     // 2*128*4 = 1024
    int vt = bid & 3;
    int mh = (bid >> 2) & 127;
    int b  = bid >> 9;
    int v0 = vt << 5;

#pragma unroll
    for (int k = 0; k < 8; k++) {
        int j  = threadIdx.x + (k << 8);
        int c  = j >> 5;
        int dy = (j >> 4) & 1;
        int x4 = j & 15;
        const float4 val = *(const float4*)(lv1 + (((size_t)(b * NC1 + c)) << 16)
                                            + ((2 * mh + dy) << 8) + (v0 << 1) + (x4 << 2));
        int vl0 = x4 << 1;                    // covers cells vl0, vl0+1
        __half2 h0 = __floats2half2_rn(val.x, val.y);
        __half2 h1 = __floats2half2_rn(val.z, val.w);
        sw[(c * 33 + vl0    ) * 2 + dy] = *(unsigned*)&h0;
        sw[(c * 33 + vl0 + 1) * 2 + dy] = *(unsigned*)&h1;
    }
    __syncthreads();

    uint2* dst = g_blkh + ((size_t)b * (LL + 1) + (mh << 7) + v0) * 64;
#pragma unroll
    for (int k = 0; k < 8; k++) {
        int j  = threadIdx.x + (k << 8);
        int vl = j >> 6;
        int c  = j & 63;
        dst[(size_t)vl * 64 + c] = s2h[c * 33 + vl];
    }
}

// ---------------------------------------------------------------------------
// k_lv2: plane-resident SMEM gather, 2 channels packed as half2 (LDS.32
// random gathers, ~3-way conflicts vs ~5 for LDS.64). fp32 accumulation.
// ---------------------------------------------------------------------------
__global__ void k_lv2(const float* __restrict__ lv2, float* __restrict__ out) {
    extern __shared__ unsigned s_plane[];            // 16385 half2 = 64 KB + 4
    int bcp = blockIdx.x;
    int cp  = bcp & 63;
    int b   = bcp >> 6;
    const float* base0 = lv2 + ((size_t)(b * NC2 + cp * 2) << 14);
    for (int i = threadIdx.x; i < LL; i += blockDim.x) {
        __half2 h = __floats2half2_rn(base0[i], base0[i + LL]);
        s_plane[i] = *(unsigned*)&h;
    }
    if (threadIdx.x == 0) s_plane[SENT] = 0u;
    __syncthreads();

    const unsigned short* tb = g_tab + (size_t)b * 9 * LL;
    float* out0 = out + ((size_t)(b * NC2 + cp * 2) << 14);
    const float inv9 = 1.0f / 9.0f;

#pragma unroll
    for (int it = 0; it < 8; it++) {
        int p1 = threadIdx.x + (it << 11);
        int p2 = p1 + 1024;
        float a0 = 0.f, a1 = 0.f, b0 = 0.f, b1 = 0.f;
#pragma unroll
        for (int tap = 0; tap < 9; tap++) {
            unsigned hv = s_plane[tb[tap * LL + p1]];
            unsigned hw2 = s_plane[tb[tap * LL + p2]];
            float2 v = __half22float2(*(__half2*)&hv);
            float2 w = __half22float2(*(__half2*)&hw2);
            a0 += v.x; a1 += v.y;
            b0 += w.x; b1 += w.y;
        }
        out0[p1]      = a0 * inv9;
        out0[p1 + LL] = a1 * inv9;
        out0[p2]      = b0 * inv9;
        out0[p2 + LL] = b1 * inv9;
    }
}

// ---------------------------------------------------------------------------
// k_lv1: warp-per-cell gather; each lane carries TWO channels (uint4 = 16B of
// fp16 per tap), so one warp covers all 64 channels: per tap one coalesced
// 512B LDG.128. 9 unconditional loads -> fp32 sum tree. Grid = 512 blocks.
// ---------------------------------------------------------------------------
__global__ void __launch_bounds__(256, 3) k_lv1(float* __restrict__ out) {
    extern __shared__ float2 sh2[];           // 128 rows x 65 float2 = 66560 B
    int bid  = blockIdx.x;                    // 2*128*2 = 512
    int vt   = bid & 1;
    int u    = (bid >> 1) & 127;
    int b    = bid >> 8;
    int v0   = vt << 6;
    int w    = threadIdx.x >> 5;
    int lane = threadIdx.x & 31;
    const unsigned short* tb = g_tab + (size_t)b * 9 * LL;
    const uint4* blkb = (const uint4*)g_blkh + ((size_t)b * (LL + 1)) * 32 + lane;
    const float inv9 = 1.0f / 9.0f;

#pragma unroll
    for (int jj = 0; jj < 8; jj++) {
        int j = (w << 3) + jj;                // local cell 0..63
        int cell = (u << 7) + v0 + j;
        uint4 t[9];
#pragma unroll
        for (int tap = 0; tap < 9; tap++) {
            unsigned off = tb[tap * LL + cell];          // warp-uniform
            t[tap] = blkb[((size_t)off) << 5];
        }
        float4 A0 = make_float4(0.f, 0.f, 0.f, 0.f);   // channel 2*lane
        float4 A1 = make_float4(0.f, 0.f, 0.f, 0.f);   // channel 2*lane+1
#pragma unroll
        for (int tap = 0; tap < 9; tap++) {
            float2 f0 = __half22float2(*(__half2*)&t[tap].x);
            float2 f1 = __half22float2(*(__half2*)&t[tap].y);
            float2 f2 = __half22float2(*(__half2*)&t[tap].z);
            float2 f3 = __half22float2(*(__half2*)&t[tap].w);
            A0.x += f0.x; A0.y += f0.y; A0.z += f1.x; A0.w += f1.y;
            A1.x += f2.x; A1.y += f2.y; A1.z += f3.x; A1.w += f3.y;
        }
        // rows r = py*64 + c (stride 65 f2), col j
        int c0 = lane << 1;
        sh2[(c0     ) * 65 + j]      = make_float2(A0.x * inv9, A0.y * inv9); // py0 c0
        sh2[(64 + c0) * 65 + j]      = make_float2(A0.z * inv9, A0.w * inv9); // py1 c0
        sh2[(c0 + 1 ) * 65 + j]      = make_float2(A1.x * inv9, A1.y * inv9); // py0 c0+1
        sh2[(65 + c0) * 65 + j]      = make_float2(A1.z * inv9, A1.w * inv9); // py1 c0+1
    }
    __syncthreads();

    // Copy-out: warp per row (128 rows), coalesced 256B float2 stores.
    for (int r = w; r < 128; r += 8) {
        int py = r >> 6;
        int c  = r & 63;
        float2* orow = (float2*)(out + (((size_t)(b * NC1 + c)) << 16)
                                 + ((2 * u + py) << 8) + (v0 << 1));
        const float2* srow = sh2 + r * 65;
        orow[lane]      = srow[lane];
        orow[lane + 32] = srow[lane + 32];
    }
}

// ---------------------------------------------------------------------------
extern "C" void kernel_launch(void* const* d_in, const int* in_sizes, int n_in,
                              void* d_out, int out_size) {
    const float* lv1 = nullptr;   // 8388608
    const float* lv2 = nullptr;   // 4194304
    const int*   hix = nullptr;   // 32768
    for (int i = 0; i < n_in; i++) {
        if (in_sizes[i] == 8388608)      lv1 = (const float*)d_in[i];
        else if (in_sizes[i] == 4194304) lv2 = (const float*)d_in[i];
        else if (in_sizes[i] == 32768)   hix = (const int*)d_in[i];
    }
    float* out = (float*)d_out;

    cudaFuncSetAttribute(k_lv2, cudaFuncAttributeMaxDynamicSharedMemorySize, 65544);
    cudaFuncSetAttribute(k_lv1, cudaFuncAttributeMaxDynamicSharedMemorySize, 66560);

    k_idx<<<128, 256>>>(hix);
    k_tab<<<128, 256>>>();
    k_blk<<<1024, 256>>>(lv1);
    k_lv2<<<128, 1024, 65544>>>(lv2, out);
    k_lv1<<<512, 256, 66560>>>(out + OUT_LV2_ELEMS);
}

// round 7
// speedup vs baseline: 1.4579x; 1.1335x over previous
#include <cuda_runtime.h>
#include <cuda_fp16.h>
#include <cstdint>

#define Hh 128
#define Ww 128
#define LL 16384          // H*W
#define NB 2
#define NC1 64
#define NC2 128
#define OUT_LV2_ELEMS 4194304
#define SENT 16384        // sentinel tap offset -> zero slot

// Scratch
__device__ unsigned short g_tab[NB * 9 * LL];                  // 576 KB tap offsets
__device__ uint2          g_blkh[(size_t)NB * (LL + 1) * 64];  // 16.8 MB half4 blocks

// ---------------------------------------------------------------------------
// k_prep: fat kernel.
//  blocks [0,1024):    space-to-depth fp16 transpose of lv1 -> g_blkh
//  blocks [1024,1056): tap-offset table from hw (dtype sniff inline) -> g_tab
// Independent writers; tab work hides under blk's DRAM-bound streaming.
// ---------------------------------------------------------------------------
__global__ void k_prep(const float* __restrict__ lv1, const int* __restrict__ hw) {
    __shared__ uint2 s2h[64 * 33];
    __shared__ int s_or;
    int bid = blockIdx.x;
    int tid = threadIdx.x;

    if (bid < 1024) {
        // ---- blk: transpose lv1 into channel-innermost fp16 blocks ----
        unsigned* sw = (unsigned*)s2h;
        int vt = bid & 3;
        int mh = (bid >> 2) & 127;
        int b  = bid >> 9;
        int v0 = vt << 5;
#pragma unroll
        for (int k = 0; k < 8; k++) {
            int j  = tid + (k << 8);
            int c  = j >> 5;
            int dy = (j >> 4) & 1;
            int x4 = j & 15;
            const float4 val = *(const float4*)(lv1 + (((size_t)(b * NC1 + c)) << 16)
                                                + ((2 * mh + dy) << 8) + (v0 << 1) + (x4 << 2));
            int vl0 = x4 << 1;
            __half2 h0 = __floats2half2_rn(val.x, val.y);
            __half2 h1 = __floats2half2_rn(val.z, val.w);
            sw[(c * 33 + vl0    ) * 2 + dy] = *(unsigned*)&h0;
            sw[(c * 33 + vl0 + 1) * 2 + dy] = *(unsigned*)&h1;
        }
        __syncthreads();
        uint2* dst = g_blkh + ((size_t)b * (LL + 1) + (mh << 7) + v0) * 64;
#pragma unroll
        for (int k = 0; k < 8; k++) {
            int j  = tid + (k << 8);
            int vl = j >> 6;
            int c  = j & 63;
            dst[(size_t)vl * 64 + c] = s2h[c * 33 + vl];
        }
    } else {
        // ---- tab: build tap-offset table directly from hw ----
        int tb = bid - 1024;                  // 0..31
        if (tid == 0) s_or = 0;
        __syncthreads();
        int acc = 0;
#pragma unroll
        for (int k = 0; k < 8; k++) acc |= hw[2 * (tid + (k << 8)) + 1];
        if (acc) atomicOr(&s_or, 1);
        __syncthreads();
        int stride = s_or ? 1 : 2;            // int32 vs int64 source

        if (tb == 0 && tid < 128) {           // zero the sentinel cells
            int b = tid >> 6, c = tid & 63;
            g_blkh[((size_t)b * (LL + 1) + LL) * 64 + c] = make_uint2(0u, 0u);
        }

#pragma unroll
        for (int k = 0; k < 4; k++) {
            int gp = (tb << 10) + (k << 8) + tid;   // 0..32767
            int b  = gp >> 14;
            int p  = gp & (LL - 1);
            int y = p >> 7, x = p & 127;
            unsigned short* tp = g_tab + (size_t)b * 9 * LL;
#pragma unroll
            for (int dy = -1; dy <= 1; dy++) {
#pragma unroll
                for (int dx = -1; dx <= 1; dx++) {
                    int tap = (dy + 1) * 3 + (dx + 1);
                    int oy = y - dy, ox = x - dx;
                    unsigned short off = SENT;
                    if ((unsigned)oy < Hh && (unsigned)ox < Ww) {
                        int m  = hw[((b << 14) + (oy << 7) + ox) * stride];
                        int sr = (m >> 7)  + dy;
                        int sc = (m & 127) + dx;
                        if ((unsigned)sr < Hh && (unsigned)sc < Ww)
                            off = (unsigned short)((sr << 7) + sc);
                    }
                    tp[tap * LL + p] = off;
                }
            }
        }
    }
}

// ---------------------------------------------------------------------------
// k_main: fat kernel, 512 threads, <=64 regs (2 blocks/SM).
//  blocks [0,128):   lv2 plane-resident SMEM gather (SMEM/L1-bound)
//  blocks [128,640): lv1 warp-coalesced L2 gather   (L2-bound)
// Co-resident per SM -> lv1 LDG warps fill lv2's latency bubbles.
// ---------------------------------------------------------------------------
__global__ void __launch_bounds__(512, 2) k_main(const float* __restrict__ lv2,
                                                 float* __restrict__ out) {
    extern __shared__ char smem_raw[];
    int bid = blockIdx.x;
    int tid = threadIdx.x;
    const float inv9 = 1.0f / 9.0f;

    if (bid < 128) {
        // ---- lv2: 2 channels packed half2, 64KB plane in SMEM ----
        unsigned* s_plane = (unsigned*)smem_raw;     // 16385 half2
        int cp  = bid & 63;
        int b   = bid >> 6;
        const float* base0 = lv2 + ((size_t)(b * NC2 + cp * 2) << 14);
        for (int i = tid; i < LL; i += 512) {
            __half2 h = __floats2half2_rn(base0[i], base0[i + LL]);
            s_plane[i] = *(unsigned*)&h;
        }
        if (tid == 0) s_plane[SENT] = 0u;
        __syncthreads();

        const unsigned short* tb = g_tab + (size_t)b * 9 * LL;
        float* out0 = out + ((size_t)(b * NC2 + cp * 2) << 14);
#pragma unroll 4
        for (int it = 0; it < 16; it++) {
            int p1 = tid + (it << 10);
            int p2 = p1 + 512;
            float a0 = 0.f, a1 = 0.f, b0 = 0.f, b1 = 0.f;
#pragma unroll
            for (int tap = 0; tap < 9; tap++) {
                unsigned hv  = s_plane[tb[tap * LL + p1]];
                unsigned hw2 = s_plane[tb[tap * LL + p2]];
                float2 v = __half22float2(*(__half2*)&hv);
                float2 w = __half22float2(*(__half2*)&hw2);
                a0 += v.x; a1 += v.y;
                b0 += w.x; b1 += w.y;
            }
            out0[p1]      = a0 * inv9;
            out0[p1 + LL] = a1 * inv9;
            out0[p2]      = b0 * inv9;
            out0[p2 + LL] = b1 * inv9;
        }
    } else {
        // ---- lv1: warp-per-cell, lane = 2 channels, taps in groups of 3 ----
        float2* sh2 = (float2*)smem_raw;             // 128 x 65 float2
        int lbid = bid - 128;                        // 0..511
        int vt   = lbid & 1;
        int u    = (lbid >> 1) & 127;
        int b    = lbid >> 8;
        int v0   = vt << 6;
        int w    = tid >> 5;                         // 0..15
        int lane = tid & 31;
        const unsigned short* tb = g_tab + (size_t)b * 9 * LL;
        const uint4* blkb = (const uint4*)g_blkh + ((size_t)b * (LL + 1)) * 32 + lane;

#pragma unroll
        for (int jj = 0; jj < 4; jj++) {
            int j = (w << 2) + jj;                   // local cell 0..63
            int cell = (u << 7) + v0 + j;
            float4 A0 = make_float4(0.f, 0.f, 0.f, 0.f);
            float4 A1 = make_float4(0.f, 0.f, 0.f, 0.f);
#pragma unroll
            for (int g = 0; g < 3; g++) {
                uint4 t0 = blkb[((size_t)tb[(3 * g + 0) * LL + cell]) << 5];
                uint4 t1 = blkb[((size_t)tb[(3 * g + 1) * LL + cell]) << 5];
                uint4 t2 = blkb[((size_t)tb[(3 * g + 2) * LL + cell]) << 5];
#pragma unroll
                for (int q = 0; q < 3; q++) {
                    uint4 t = (q == 0) ? t0 : (q == 1) ? t1 : t2;
                    float2 f0 = __half22float2(*(__half2*)&t.x);
                    float2 f1 = __half22float2(*(__half2*)&t.y);
                    float2 f2 = __half22float2(*(__half2*)&t.z);
                    float2 f3 = __half22float2(*(__half2*)&t.w);
                    A0.x += f0.x; A0.y += f0.y; A0.z += f1.x; A0.w += f1.y;
                    A1.x += f2.x; A1.y += f2.y; A1.z += f3.x; A1.w += f3.y;
                }
            }
            int c0 = lane << 1;
            sh2[(c0     ) * 65 + j] = make_float2(A0.x * inv9, A0.y * inv9); // py0 c0
            sh2[(64 + c0) * 65 + j] = make_float2(A0.z * inv9, A0.w * inv9); // py1 c0
            sh2[(c0 + 1 ) * 65 + j] = make_float2(A1.x * inv9, A1.y * inv9); // py0 c0+1
            sh2[(65 + c0) * 65 + j] = make_float2(A1.z * inv9, A1.w * inv9); // py1 c0+1
        }
        __syncthreads();

        // Copy-out: warp per row, coalesced 256B float2 stores.
        for (int r = w; r < 128; r += 16) {
            int py = r >> 6;
            int c  = r & 63;
            float2* orow = (float2*)(out + OUT_LV2_ELEMS
                                     + (((size_t)(b * NC1 + c)) << 16)
                                     + ((2 * u + py) << 8) + (v0 << 1));
            const float2* srow = sh2 + r * 65;
            orow[lane]      = srow[lane];
            orow[lane + 32] = srow[lane + 32];
        }
    }
}

// ---------------------------------------------------------------------------
extern "C" void kernel_launch(void* const* d_in, const int* in_sizes, int n_in,
                              void* d_out, int out_size) {
    const float* lv1 = nullptr;   // 8388608
    const float* lv2 = nullptr;   // 4194304
    const int*   hix = nullptr;   // 32768
    for (int i = 0; i < n_in; i++) {
        if (in_sizes[i] == 8388608)      lv1 = (const float*)d_in[i];
        else if (in_sizes[i] == 4194304) lv2 = (const float*)d_in[i];
        else if (in_sizes[i] == 32768)   hix = (const int*)d_in[i];
    }
    float* out = (float*)d_out;

    cudaFuncSetAttribute(k_main, cudaFuncAttributeMaxDynamicSharedMemorySize, 66560);

    k_prep<<<1056, 256>>>(lv1, hix);
    k_main<<<640, 512, 66560>>>(lv2, out);
}

// round 8
// speedup vs baseline: 1.5439x; 1.0589x over previous
#include <cuda_runtime.h>
#include <cuda_fp16.h>
#include <cstdint>

#define Hh 128
#define Ww 128
#define LL 16384          // H*W
#define NB 2
#define NC1 64
#define NC2 128
#define OUT_LV2_ELEMS 4194304
#define SENT 16384        // sentinel tap offset -> zero slot

// Scratch
__device__ unsigned short g_tab[NB * 9 * LL];                  // 576 KB tap offsets
__device__ uint2          g_blkh[(size_t)NB * (LL + 1) * 64];  // 16.8 MB half4 blocks

// ---------------------------------------------------------------------------
// k_tab: tap-offset table straight from hw (dtype sniff inline) + sentinel
// zeroing of g_blkh. 32 blocks, ~2us.
// ---------------------------------------------------------------------------
__global__ void k_tab(const int* __restrict__ hw) {
    __shared__ int s_or;
    int tid = threadIdx.x;
    if (tid == 0) s_or = 0;
    __syncthreads();
    int acc = 0;
#pragma unroll
    for (int k = 0; k < 8; k++) acc |= hw[2 * (tid + (k << 8)) + 1];
    if (acc) atomicOr(&s_or, 1);
    __syncthreads();
    int stride = s_or ? 1 : 2;                // int32 vs int64 source

    if (blockIdx.x == 0 && tid < 128) {       // zero sentinel cells
        int b = tid >> 6, c = tid & 63;
        g_blkh[((size_t)b * (LL + 1) + LL) * 64 + c] = make_uint2(0u, 0u);
    }

#pragma unroll
    for (int k = 0; k < 4; k++) {
        int gp = (blockIdx.x << 10) + (k << 8) + tid;   // 0..32767
        int b  = gp >> 14;
        int p  = gp & (LL - 1);
        int y = p >> 7, x = p & 127;
        unsigned short* tp = g_tab + (size_t)b * 9 * LL;
#pragma unroll
        for (int dy = -1; dy <= 1; dy++) {
#pragma unroll
            for (int dx = -1; dx <= 1; dx++) {
                int tap = (dy + 1) * 3 + (dx + 1);
                int oy = y - dy, ox = x - dx;
                unsigned short off = SENT;
                if ((unsigned)oy < Hh && (unsigned)ox < Ww) {
                    int m  = hw[((b << 14) + (oy << 7) + ox) * stride];
                    int sr = (m >> 7)  + dy;
                    int sc = (m & 127) + dx;
                    if ((unsigned)sr < Hh && (unsigned)sc < Ww)
                        off = (unsigned short)((sr << 7) + sc);
                }
                tp[tap * LL + p] = off;
            }
        }
    }
}

// ---------------------------------------------------------------------------
// k_blk: space-to-depth fp16 transpose of lv1 -> g_blkh (DRAM-streaming).
// ---------------------------------------------------------------------------
__global__ void k_blk(const float* __restrict__ lv1) {
    __shared__ uint2 s2h[64 * 33];
    unsigned* sw = (unsigned*)s2h;
    int bid = blockIdx.x;                     // 1024
    int tid = threadIdx.x;
    int vt = bid & 3;
    int mh = (bid >> 2) & 127;
    int b  = bid >> 9;
    int v0 = vt << 5;

#pragma unroll
    for (int k = 0; k < 8; k++) {
        int j  = tid + (k << 8);
        int c  = j >> 5;
        int dy = (j >> 4) & 1;
        int x4 = j & 15;
        const float4 val = *(const float4*)(lv1 + (((size_t)(b * NC1 + c)) << 16)
                                            + ((2 * mh + dy) << 8) + (v0 << 1) + (x4 << 2));
        int vl0 = x4 << 1;
        __half2 h0 = __floats2half2_rn(val.x, val.y);
        __half2 h1 = __floats2half2_rn(val.z, val.w);
        sw[(c * 33 + vl0    ) * 2 + dy] = *(unsigned*)&h0;
        sw[(c * 33 + vl0 + 1) * 2 + dy] = *(unsigned*)&h1;
    }
    __syncthreads();

    uint2* dst = g_blkh + ((size_t)b * (LL + 1) + (mh << 7) + v0) * 64;
#pragma unroll
    for (int k = 0; k < 8; k++) {
        int j  = tid + (k << 8);
        int vl = j >> 6;
        int c  = j & 63;
        dst[(size_t)vl * 64 + c] = s2h[c * 33 + vl];
    }
}

// ---------------------------------------------------------------------------
// k_lv2: plane-resident SMEM gather, 2 channels packed half2, 1024 threads.
// ---------------------------------------------------------------------------
__global__ void k_lv2(const float* __restrict__ lv2, float* __restrict__ out) {
    extern __shared__ unsigned s_plane[];            // 16385 half2
    int bcp = blockIdx.x;
    int cp  = bcp & 63;
    int b   = bcp >> 6;
    const float* base0 = lv2 + ((size_t)(b * NC2 + cp * 2) << 14);
    for (int i = threadIdx.x; i < LL; i += blockDim.x) {
        __half2 h = __floats2half2_rn(base0[i], base0[i + LL]);
        s_plane[i] = *(unsigned*)&h;
    }
    if (threadIdx.x == 0) s_plane[SENT] = 0u;
    __syncthreads();

    const unsigned short* tb = g_tab + (size_t)b * 9 * LL;
    float* out0 = out + ((size_t)(b * NC2 + cp * 2) << 14);
    const float inv9 = 1.0f / 9.0f;

#pragma unroll
    for (int it = 0; it < 8; it++) {
        int p1 = threadIdx.x + (it << 11);
        int p2 = p1 + 1024;
        float a0 = 0.f, a1 = 0.f, b0 = 0.f, b1 = 0.f;
#pragma unroll
        for (int tap = 0; tap < 9; tap++) {
            unsigned hv  = s_plane[tb[tap * LL + p1]];
            unsigned hw2 = s_plane[tb[tap * LL + p2]];
            float2 v = __half22float2(*(__half2*)&hv);
            float2 w = __half22float2(*(__half2*)&hw2);
            a0 += v.x; a1 += v.y;
            b0 += w.x; b1 += w.y;
        }
        out0[p1]      = a0 * inv9;
        out0[p1 + LL] = a1 * inv9;
        out0[p2]      = b0 * inv9;
        out0[p2 + LL] = b1 * inv9;
    }
}

// ---------------------------------------------------------------------------
// k_lv1: warp-per-cell gather; lane = 2 channels (uint4/tap), one coalesced
// 512B LDG.128 per tap, 9 unconditional loads in flight -> fp32 sum tree.
// ---------------------------------------------------------------------------
__global__ void __launch_bounds__(256, 3) k_lv1(float* __restrict__ out) {
    extern __shared__ float2 sh2[];           // 128 rows x 65 float2 = 66560 B
    int bid  = blockIdx.x;                    // 2*128*2 = 512
    int vt   = bid & 1;
    int u    = (bid >> 1) & 127;
    int b    = bid >> 8;
    int v0   = vt << 6;
    int w    = threadIdx.x >> 5;
    int lane = threadIdx.x & 31;
    const unsigned short* tb = g_tab + (size_t)b * 9 * LL;
    const uint4* blkb = (const uint4*)g_blkh + ((size_t)b * (LL + 1)) * 32 + lane;
    const float inv9 = 1.0f / 9.0f;

#pragma unroll
    for (int jj = 0; jj < 8; jj++) {
        int j = (w << 3) + jj;                // local cell 0..63
        int cell = (u << 7) + v0 + j;
        uint4 t[9];
#pragma unroll
        for (int tap = 0; tap < 9; tap++) {
            unsigned off = tb[tap * LL + cell];          // warp-uniform
            t[tap] = blkb[((size_t)off) << 5];
        }
        float4 A0 = make_float4(0.f, 0.f, 0.f, 0.f);   // channel 2*lane
        float4 A1 = make_float4(0.f, 0.f, 0.f, 0.f);   // channel 2*lane+1
#pragma unroll
        for (int tap = 0; tap < 9; tap++) {
            float2 f0 = __half22float2(*(__half2*)&t[tap].x);
            float2 f1 = __half22float2(*(__half2*)&t[tap].y);
            float2 f2 = __half22float2(*(__half2*)&t[tap].z);
            float2 f3 = __half22float2(*(__half2*)&t[tap].w);
            A0.x += f0.x; A0.y += f0.y; A0.z += f1.x; A0.w += f1.y;
            A1.x += f2.x; A1.y += f2.y; A1.z += f3.x; A1.w += f3.y;
        }
        int c0 = lane << 1;
        sh2[(c0     ) * 65 + j] = make_float2(A0.x * inv9, A0.y * inv9); // py0 c0
        sh2[(64 + c0) * 65 + j] = make_float2(A0.z * inv9, A0.w * inv9); // py1 c0
        sh2[(c0 + 1 ) * 65 + j] = make_float2(A1.x * inv9, A1.y * inv9); // py0 c0+1
        sh2[(65 + c0) * 65 + j] = make_float2(A1.z * inv9, A1.w * inv9); // py1 c0+1
    }
    __syncthreads();

    for (int r = w; r < 128; r += 8) {
        int py = r >> 6;
        int c  = r & 63;
        float2* orow = (float2*)(out + (((size_t)(b * NC1 + c)) << 16)
                                 + ((2 * u + py) << 8) + (v0 << 1));
        const float2* srow = sh2 + r * 65;
        orow[lane]      = srow[lane];
        orow[lane + 32] = srow[lane + 32];
    }
}

// ---------------------------------------------------------------------------
// Launch DAG (fork/join, capture-legal):
//   stream0: evFork -> k_tab -> evTab -> k_lv2 -> (wait evDone)
//   s2:      (wait evFork) -> k_blk -> (wait evTab) -> k_lv1 -> evDone
// Streams/events created lazily on the first (uncaptured correctness) call.
// ---------------------------------------------------------------------------
extern "C" void kernel_launch(void* const* d_in, const int* in_sizes, int n_in,
                              void* d_out, int out_size) {
    const float* lv1 = nullptr;   // 8388608
    const float* lv2 = nullptr;   // 4194304
    const int*   hix = nullptr;   // 32768
    for (int i = 0; i < n_in; i++) {
        if (in_sizes[i] == 8388608)      lv1 = (const float*)d_in[i];
        else if (in_sizes[i] == 4194304) lv2 = (const float*)d_in[i];
        else if (in_sizes[i] == 32768)   hix = (const int*)d_in[i];
    }
    float* out = (float*)d_out;

    static cudaStream_t s2 = nullptr;
    static cudaEvent_t evFork = nullptr, evTab = nullptr, evDone = nullptr;
    if (!s2) {
        cudaStreamCreateWithFlags(&s2, cudaStreamNonBlocking);
        cudaEventCreateWithFlags(&evFork, cudaEventDisableTiming);
        cudaEventCreateWithFlags(&evTab,  cudaEventDisableTiming);
        cudaEventCreateWithFlags(&evDone, cudaEventDisableTiming);
        cudaFuncSetAttribute(k_lv2, cudaFuncAttributeMaxDynamicSharedMemorySize, 65544);
        cudaFuncSetAttribute(k_lv1, cudaFuncAttributeMaxDynamicSharedMemorySize, 66560);
    }

    cudaEventRecord(evFork, 0);
    cudaStreamWaitEvent(s2, evFork, 0);

    k_blk<<<1024, 256, 0, s2>>>(lv1);          // s2: DRAM-bound transpose

    k_tab<<<32, 256>>>(hix);                   // stream0: tiny table build
    cudaEventRecord(evTab, 0);
    cudaStreamWaitEvent(s2, evTab, 0);

    k_lv2<<<128, 1024, 65544>>>(lv2, out);     // stream0: LDS-bound gather

    k_lv1<<<512, 256, 66560, s2>>>(out + OUT_LV2_ELEMS);  // s2: L2-bound gather
    cudaEventRecord(evDone, s2);
    cudaStreamWaitEvent(0, evDone, 0);
}